// round 1
// baseline (speedup 1.0000x reference)
#include <cuda_runtime.h>
#include <math.h>

#define L_STEPS 512
#define BATCH   128
#define HID     512
#define DIN     512

// ---------------- device scratch (static allocation — allowed) ----------------
__device__ float g_h[2][BATCH * HID];          // ping-pong hidden state, 512KB
__device__ unsigned g_bar_arrive = 0;
__device__ volatile unsigned g_bar_gen = 0;

#define SCAN_BLOCKS 128
#define SCAN_THREADS 128
// ws: 32 rows x 516 floats (padded), hs: 16 x 512
#define WS_STRIDE_F4 129                        // 516 floats / 4
#define SMEM_FLOATS (32 * 516 + 16 * 512)
#define SMEM_BYTES  (SMEM_FLOATS * 4)

// ---------------- grid barrier (all 128 CTAs co-resident: 128 <= 148 SMs) -----
__device__ __forceinline__ void grid_barrier() {
    __threadfence();          // publish this thread's global writes
    __syncthreads();          // everyone in block done + fenced
    if (threadIdx.x == 0) {
        unsigned gen = g_bar_gen;
        if (atomicAdd(&g_bar_arrive, 1u) == SCAN_BLOCKS - 1) {
            g_bar_arrive = 0;
            __threadfence();
            g_bar_gen = gen + 1;
        } else {
            while (g_bar_gen == gen) { __nanosleep(64); }
        }
    }
    __syncthreads();
}

// ---------------- Phase 1: xproj = x @ Wx^T + bx + bh -------------------------
// A = x as [M=65536, K=512]; B = Wx_w [N=512, K=512]; C[m,n] += biases
__global__ void __launch_bounds__(256) xproj_kernel(
    const float* __restrict__ x, const float* __restrict__ Wx,
    const float* __restrict__ bx, const float* __restrict__ bh,
    float* __restrict__ out)
{
    __shared__ float As[16][64];
    __shared__ float Bs[16][64];

    const int tid = threadIdx.x;
    const int tx = tid & 15, ty = tid >> 4;
    const int m0 = blockIdx.y << 6;
    const int n0 = blockIdx.x << 6;
    const int lrow = tid >> 2, lc = tid & 3;

    const float* aptr = x + (size_t)(m0 + lrow) * DIN;
    const float* bptr = Wx + (size_t)(n0 + lrow) * DIN;

    float acc[4][4] = {};

    for (int k0 = 0; k0 < DIN; k0 += 16) {
        float4 av = __ldg((const float4*)(aptr + k0) + lc);
        float4 bv = __ldg((const float4*)(bptr + k0) + lc);
        __syncthreads();   // previous iteration's reads complete before overwrite
        As[lc * 4 + 0][lrow] = av.x; As[lc * 4 + 1][lrow] = av.y;
        As[lc * 4 + 2][lrow] = av.z; As[lc * 4 + 3][lrow] = av.w;
        Bs[lc * 4 + 0][lrow] = bv.x; Bs[lc * 4 + 1][lrow] = bv.y;
        Bs[lc * 4 + 2][lrow] = bv.z; Bs[lc * 4 + 3][lrow] = bv.w;
        __syncthreads();

        #pragma unroll
        for (int kk = 0; kk < 16; ++kk) {
            float a[4], b[4];
            *(float4*)a = *(const float4*)&As[kk][ty << 2];
            *(float4*)b = *(const float4*)&Bs[kk][tx << 2];
            #pragma unroll
            for (int i = 0; i < 4; ++i)
                #pragma unroll
                for (int j = 0; j < 4; ++j)
                    acc[i][j] = fmaf(a[i], b[j], acc[i][j]);
        }
    }

    const int n = n0 + (tx << 2);
    float4 bxv = *(const float4*)(bx + n);
    float4 bhv = *(const float4*)(bh + n);
    float bias[4] = { bxv.x + bhv.x, bxv.y + bhv.y, bxv.z + bhv.z, bxv.w + bhv.w };

    #pragma unroll
    for (int i = 0; i < 4; ++i) {
        float4 o;
        o.x = acc[i][0] + bias[0];
        o.y = acc[i][1] + bias[1];
        o.z = acc[i][2] + bias[2];
        o.w = acc[i][3] + bias[3];
        *(float4*)(out + (size_t)(m0 + (ty << 2) + i) * HID + n) = o;
    }
}

// ---------------- Phase 2: persistent scan ------------------------------------
// 128 CTAs: (bt 0..7) x (ht 0..15). CTA owns batch rows b0..b0+15, cols j0..j0+31.
// Wh slice [32 x 512] resident in SMEM for all 512 steps.
__global__ void __launch_bounds__(SCAN_THREADS) rnn_scan_kernel(
    const float* __restrict__ h0, const float* __restrict__ Wh,
    float* __restrict__ out)
{
    extern __shared__ float sm[];
    float* ws = sm;                       // 32 * 516 floats (padded rows)
    float* hs = sm + 32 * 516;            // 16 * 512 floats

    const int tid  = threadIdx.x;
    const int lane = tid & 31;
    const int w    = tid >> 5;            // warp 0..3
    const int bt = blockIdx.x >> 4;
    const int ht = blockIdx.x & 15;
    const int b0 = bt << 4;               // 16 batch rows
    const int j0 = ht << 5;               // 32 output cols

    // init g_h[0] <- input h (16384 float4 total, exactly 1 per thread chip-wide)
    {
        float4* dst = (float4*)g_h[0];
        const float4* src = (const float4*)h0;
        int idx = blockIdx.x * SCAN_THREADS + tid;
        dst[idx] = __ldg(src + idx);
    }
    // load Wh slice into smem (rows j0..j0+31), padded row stride 129 float4
    {
        const float4* whp = (const float4*)(Wh + (size_t)j0 * HID);
        float4* ws4 = (float4*)ws;
        for (int i = tid; i < 32 * 128; i += SCAN_THREADS) {
            int j = i >> 7, k4 = i & 127;
            ws4[j * WS_STRIDE_F4 + k4] = __ldg(whp + j * 128 + k4);
        }
    }
    grid_barrier();

    const float4* wrow = (const float4*)ws + lane * WS_STRIDE_F4;
    const int j = j0 + lane;
    int p = 0;

    for (int t = 0; t < L_STEPS; ++t) {
        // load h tile (16 contiguous rows) from ping buffer, L1-bypassing
        {
            const float4* gh = (const float4*)(g_h[p] + b0 * HID);
            float4* hs4 = (float4*)hs;
            #pragma unroll
            for (int i = 0; i < 16; ++i)
                hs4[tid + i * 128] = __ldcg(gh + tid + i * 128);
        }
        __syncthreads();

        float acc[4] = {0.f, 0.f, 0.f, 0.f};
        const float4* hr0 = (const float4*)hs + (w + 0)  * 128;
        const float4* hr1 = (const float4*)hs + (w + 4)  * 128;
        const float4* hr2 = (const float4*)hs + (w + 8)  * 128;
        const float4* hr3 = (const float4*)hs + (w + 12) * 128;

        #pragma unroll 4
        for (int k4 = 0; k4 < 128; ++k4) {
            float4 wv = wrow[k4];
            float4 a = hr0[k4], b = hr1[k4], c = hr2[k4], d = hr3[k4];
            acc[0] = fmaf(a.x, wv.x, acc[0]); acc[0] = fmaf(a.y, wv.y, acc[0]);
            acc[0] = fmaf(a.z, wv.z, acc[0]); acc[0] = fmaf(a.w, wv.w, acc[0]);
            acc[1] = fmaf(b.x, wv.x, acc[1]); acc[1] = fmaf(b.y, wv.y, acc[1]);
            acc[1] = fmaf(b.z, wv.z, acc[1]); acc[1] = fmaf(b.w, wv.w, acc[1]);
            acc[2] = fmaf(c.x, wv.x, acc[2]); acc[2] = fmaf(c.y, wv.y, acc[2]);
            acc[2] = fmaf(c.z, wv.z, acc[2]); acc[2] = fmaf(c.w, wv.w, acc[2]);
            acc[3] = fmaf(d.x, wv.x, acc[3]); acc[3] = fmaf(d.y, wv.y, acc[3]);
            acc[3] = fmaf(d.z, wv.z, acc[3]); acc[3] = fmaf(d.w, wv.w, acc[3]);
        }

        // epilogue: hnew = tanh(acc + xp); xp lives in out[t] and is overwritten in place
        float* gout = out + (size_t)t * (BATCH * HID);
        float* ghn  = g_h[p ^ 1];
        #pragma unroll
        for (int r = 0; r < 4; ++r) {
            const int b = b0 + w + (r << 2);
            const size_t off = (size_t)b * HID + j;
            float hn = tanhf(acc[r] + gout[off]);
            gout[off] = hn;          // hAll[t]
            ghn[off]  = hn;          // next-step state
            if (t == L_STEPS - 1)
                out[(size_t)L_STEPS * BATCH * HID + off] = hn;   // h_last
        }

        grid_barrier();
        p ^= 1;
    }
}

// ---------------- launch -------------------------------------------------------
extern "C" void kernel_launch(void* const* d_in, const int* in_sizes, int n_in,
                              void* d_out, int out_size)
{
    const float* x   = (const float*)d_in[0];
    const float* h0  = (const float*)d_in[1];
    const float* Wxw = (const float*)d_in[2];
    const float* Wxb = (const float*)d_in[3];
    const float* Whw = (const float*)d_in[4];
    const float* Whb = (const float*)d_in[5];
    float* out = (float*)d_out;

    // Phase 1: xproj -> out[0 .. L*B*H)
    dim3 g1(HID / 64, (L_STEPS * BATCH) / 64);
    xproj_kernel<<<g1, 256>>>(x, Wxw, Wxb, Whb, out);

    // Phase 2: persistent scan (overwrites xproj in place, appends h_last)
    cudaFuncSetAttribute(rnn_scan_kernel,
                         cudaFuncAttributeMaxDynamicSharedMemorySize, SMEM_BYTES);
    rnn_scan_kernel<<<SCAN_BLOCKS, SCAN_THREADS, SMEM_BYTES>>>(h0, Whw, out);
}

// round 2
// speedup vs baseline: 1.0138x; 1.0138x over previous
#include <cuda_runtime.h>
#include <math.h>

#define L_STEPS 512
#define BATCH   128
#define HID     512
#define DIN     512

// ---------------- device scratch ----------------
__device__ float g_h[2][BATCH * HID];          // ping-pong hidden state
__device__ unsigned g_bar_arrive = 0;
__device__ volatile unsigned g_bar_gen = 0;

#define SCAN_BLOCKS 128
#define SCAN_THREADS 128
// ws4: k-major W tile, 128 k4-groups x 32 cols of float4 (64KB), conflict-free
// hs : 16 rows x 512 floats (32KB)
#define WS_F4   (128 * 32)
#define SMEM_BYTES (WS_F4 * 16 + 16 * 512 * 4)

// ---------------- grid barrier (128 CTAs co-resident on 148 SMs) -----
__device__ __forceinline__ void grid_barrier() {
    __threadfence();
    __syncthreads();
    if (threadIdx.x == 0) {
        unsigned gen = g_bar_gen;
        if (atomicAdd(&g_bar_arrive, 1u) == SCAN_BLOCKS - 1) {
            g_bar_arrive = 0;
            __threadfence();
            g_bar_gen = gen + 1;
        } else {
            while (g_bar_gen == gen) { __nanosleep(32); }
        }
    }
    __syncthreads();
}

// ---------------- Phase 1: xproj = x @ Wx^T + bx + bh -------------------------
// 128x64 tile, 256 threads, 8x4 register tile per thread.
__global__ void __launch_bounds__(256) xproj_kernel(
    const float* __restrict__ x, const float* __restrict__ Wx,
    const float* __restrict__ bx, const float* __restrict__ bh,
    float* __restrict__ out)
{
    __shared__ float As[16][128];   // k-major A tile
    __shared__ float Bs[16][64];    // k-major B tile

    const int tid = threadIdx.x;
    const int tx = tid & 15;        // col group (4 cols)
    const int ty = tid >> 4;        // row group (8 rows)
    const int m0 = blockIdx.y << 7;
    const int n0 = blockIdx.x << 6;

    // A loads: 512 float4 per k-tile -> 2 per thread
    const int aRow = tid >> 2;          // 0..63
    const int aK4  = tid & 3;           // 0..3
    const float* aG0 = x + (size_t)(m0 + aRow) * DIN + aK4 * 4;
    const float* aG1 = aG0 + (size_t)64 * DIN;
    // B loads: 256 float4 per k-tile -> 1 per thread
    const int bRow = tid >> 2;          // 0..63
    const float* bG = Wx + (size_t)(n0 + bRow) * DIN + aK4 * 4;

    float acc[8][4] = {};

    for (int k0 = 0; k0 < DIN; k0 += 16) {
        float4 av0 = __ldg((const float4*)(aG0 + k0));
        float4 av1 = __ldg((const float4*)(aG1 + k0));
        float4 bv  = __ldg((const float4*)(bG + k0));
        __syncthreads();
        As[aK4 * 4 + 0][aRow]      = av0.x;
        As[aK4 * 4 + 1][aRow]      = av0.y;
        As[aK4 * 4 + 2][aRow]      = av0.z;
        As[aK4 * 4 + 3][aRow]      = av0.w;
        As[aK4 * 4 + 0][aRow + 64] = av1.x;
        As[aK4 * 4 + 1][aRow + 64] = av1.y;
        As[aK4 * 4 + 2][aRow + 64] = av1.z;
        As[aK4 * 4 + 3][aRow + 64] = av1.w;
        Bs[aK4 * 4 + 0][bRow] = bv.x;
        Bs[aK4 * 4 + 1][bRow] = bv.y;
        Bs[aK4 * 4 + 2][bRow] = bv.z;
        Bs[aK4 * 4 + 3][bRow] = bv.w;
        __syncthreads();

        #pragma unroll
        for (int kk = 0; kk < 16; ++kk) {
            float a[8], b[4];
            *(float4*)&a[0] = *(const float4*)&As[kk][ty << 3];
            *(float4*)&a[4] = *(const float4*)&As[kk][(ty << 3) + 4];
            *(float4*)&b[0] = *(const float4*)&Bs[kk][tx << 2];
            #pragma unroll
            for (int i = 0; i < 8; ++i)
                #pragma unroll
                for (int j = 0; j < 4; ++j)
                    acc[i][j] = fmaf(a[i], b[j], acc[i][j]);
        }
    }

    const int n = n0 + (tx << 2);
    float4 bxv = *(const float4*)(bx + n);
    float4 bhv = *(const float4*)(bh + n);
    const float b0f = bxv.x + bhv.x, b1f = bxv.y + bhv.y;
    const float b2f = bxv.z + bhv.z, b3f = bxv.w + bhv.w;

    #pragma unroll
    for (int i = 0; i < 8; ++i) {
        float4 o;
        o.x = acc[i][0] + b0f;
        o.y = acc[i][1] + b1f;
        o.z = acc[i][2] + b2f;
        o.w = acc[i][3] + b3f;
        *(float4*)(out + (size_t)(m0 + (ty << 3) + i) * HID + n) = o;
    }
}

// ---------------- Phase 2: persistent scan ------------------------------------
// 128 CTAs: (bt 0..7) x (ht 0..15). CTA owns 16 batch rows, 32 output cols.
// W slice stored k-major in smem: ws4[k4*32 + col] -> conflict-free LDS.128.
__global__ void __launch_bounds__(SCAN_THREADS) rnn_scan_kernel(
    const float* __restrict__ h0, const float* __restrict__ Wh,
    float* __restrict__ out)
{
    extern __shared__ float sm[];
    float4* ws4 = (float4*)sm;                 // 128*32 float4, k-major
    float*  hs  = sm + WS_F4 * 4;              // 16 x 512

    const int tid  = threadIdx.x;
    const int lane = tid & 31;
    const int w    = tid >> 5;            // warp 0..3
    const int bt = blockIdx.x >> 4;
    const int ht = blockIdx.x & 15;
    const int b0 = bt << 4;               // 16 batch rows
    const int j0 = ht << 5;               // 32 output cols

    // init g_h[0] <- input h
    {
        float4* dst = (float4*)g_h[0];
        const float4* src = (const float4*)h0;
        int idx = blockIdx.x * SCAN_THREADS + tid;
        dst[idx] = __ldg(src + idx);
    }
    // load Wh slice, transposed to k-major: ws4[k4*32 + j] = W[j0+j][4k4..4k4+3]
    {
        const float4* whp = (const float4*)(Wh + (size_t)j0 * HID);
        for (int i = tid; i < 32 * 128; i += SCAN_THREADS) {
            int j = i >> 7, k4 = i & 127;
            ws4[k4 * 32 + j] = __ldg(whp + j * 128 + k4);   // coalesced global read
        }
    }
    grid_barrier();

    const float4* wcol = ws4 + lane;      // column j0+lane, stride 32 f4 per k4
    const int j = j0 + lane;
    int p = 0;

    for (int t = 0; t < L_STEPS; ++t) {
        // stage h tile (16 rows) into smem
        {
            const float4* gh = (const float4*)(g_h[p] + b0 * HID);
            float4* hs4 = (float4*)hs;
            #pragma unroll
            for (int i = 0; i < 16; ++i)
                hs4[tid + i * 128] = __ldcg(gh + tid + i * 128);
        }
        __syncthreads();

        float acc[4] = {0.f, 0.f, 0.f, 0.f};
        const float4* hr0 = (const float4*)hs + (w + 0)  * 128;
        const float4* hr1 = (const float4*)hs + (w + 4)  * 128;
        const float4* hr2 = (const float4*)hs + (w + 8)  * 128;
        const float4* hr3 = (const float4*)hs + (w + 12) * 128;

        #pragma unroll 8
        for (int k4 = 0; k4 < 128; ++k4) {
            float4 wv = wcol[k4 * 32];                       // conflict-free
            float4 a = hr0[k4], b = hr1[k4], c = hr2[k4], d = hr3[k4];  // broadcasts
            acc[0] = fmaf(a.x, wv.x, acc[0]); acc[0] = fmaf(a.y, wv.y, acc[0]);
            acc[0] = fmaf(a.z, wv.z, acc[0]); acc[0] = fmaf(a.w, wv.w, acc[0]);
            acc[1] = fmaf(b.x, wv.x, acc[1]); acc[1] = fmaf(b.y, wv.y, acc[1]);
            acc[1] = fmaf(b.z, wv.z, acc[1]); acc[1] = fmaf(b.w, wv.w, acc[1]);
            acc[2] = fmaf(c.x, wv.x, acc[2]); acc[2] = fmaf(c.y, wv.y, acc[2]);
            acc[2] = fmaf(c.z, wv.z, acc[2]); acc[2] = fmaf(c.w, wv.w, acc[2]);
            acc[3] = fmaf(d.x, wv.x, acc[3]); acc[3] = fmaf(d.y, wv.y, acc[3]);
            acc[3] = fmaf(d.z, wv.z, acc[3]); acc[3] = fmaf(d.w, wv.w, acc[3]);
        }

        // epilogue: hnew = tanh(acc + xp), xp in out[t], overwritten in place
        float* gout = out + (size_t)t * (BATCH * HID);
        float* ghn  = g_h[p ^ 1];
        #pragma unroll
        for (int r = 0; r < 4; ++r) {
            const int b = b0 + w + (r << 2);
            const size_t off = (size_t)b * HID + j;
            float hn = tanhf(acc[r] + gout[off]);
            gout[off] = hn;          // hAll[t]
            ghn[off]  = hn;          // next-step state
            if (t == L_STEPS - 1)
                out[(size_t)L_STEPS * BATCH * HID + off] = hn;   // h_last
        }

        grid_barrier();
        p ^= 1;
    }
}

// ---------------- launch -------------------------------------------------------
extern "C" void kernel_launch(void* const* d_in, const int* in_sizes, int n_in,
                              void* d_out, int out_size)
{
    const float* x   = (const float*)d_in[0];
    const float* h0  = (const float*)d_in[1];
    const float* Wxw = (const float*)d_in[2];
    const float* Wxb = (const float*)d_in[3];
    const float* Whw = (const float*)d_in[4];
    const float* Whb = (const float*)d_in[5];
    float* out = (float*)d_out;

    // Phase 1: xproj -> out[0 .. L*B*H)
    dim3 g1(HID / 64, (L_STEPS * BATCH) / 128);
    xproj_kernel<<<g1, 256>>>(x, Wxw, Wxb, Whb, out);

    // Phase 2: persistent scan (overwrites xproj in place, appends h_last)
    cudaFuncSetAttribute(rnn_scan_kernel,
                         cudaFuncAttributeMaxDynamicSharedMemorySize, SMEM_BYTES);
    rnn_scan_kernel<<<SCAN_BLOCKS, SCAN_THREADS, SMEM_BYTES>>>(h0, Whw, out);
}

// round 3
// speedup vs baseline: 1.7627x; 1.7387x over previous
#include <cuda_runtime.h>
#include <math.h>

#define L_STEPS 512
#define BATCH   128
#define HID     512
#define DIN     512

// ---------------- device scratch ----------------
__device__ float g_h[2][BATCH * HID];          // ping-pong hidden state
__device__ unsigned g_bar_arrive = 0;
__device__ volatile unsigned g_bar_gen = 0;

#define SCAN_BLOCKS  128
#define SCAN_THREADS 256

// smem layout (floats):
//   ws: 32 cols x 516  (W slice, row = output col, padded)   66048 B
//   hs: 16 rows x 516  (h tile, padded)                      33024 B
//   red: 8 warps x 576 (reduction scratch, 16 rows x 36)     18432 B
#define WS_STRIDE_F4 129
#define HS_STRIDE_F4 129
#define WS_FLOATS (32 * 516)
#define HS_FLOATS (16 * 516)
#define RED_ROW    36
#define RED_WARP   (16 * RED_ROW)            // 576
#define RED_FLOATS (8 * RED_WARP)
#define SMEM_BYTES ((WS_FLOATS + HS_FLOATS + RED_FLOATS) * 4)

// ---------------- grid barrier (128 CTAs co-resident on 148 SMs) -----
__device__ __forceinline__ void grid_barrier() {
    __threadfence();
    __syncthreads();
    if (threadIdx.x == 0) {
        unsigned gen = g_bar_gen;
        if (atomicAdd(&g_bar_arrive, 1u) == SCAN_BLOCKS - 1) {
            g_bar_arrive = 0;
            __threadfence();
            g_bar_gen = gen + 1;
        } else {
            while (g_bar_gen == gen) { __nanosleep(32); }
        }
    }
    __syncthreads();
}

// ---------------- Phase 1: xproj = x @ Wx^T + bx + bh -------------------------
__global__ void __launch_bounds__(256) xproj_kernel(
    const float* __restrict__ x, const float* __restrict__ Wx,
    const float* __restrict__ bx, const float* __restrict__ bh,
    float* __restrict__ out)
{
    __shared__ float As[16][128];
    __shared__ float Bs[16][64];

    const int tid = threadIdx.x;
    const int tx = tid & 15;
    const int ty = tid >> 4;
    const int m0 = blockIdx.y << 7;
    const int n0 = blockIdx.x << 6;

    const int aRow = tid >> 2;
    const int aK4  = tid & 3;
    const float* aG0 = x + (size_t)(m0 + aRow) * DIN + aK4 * 4;
    const float* aG1 = aG0 + (size_t)64 * DIN;
    const float* bG = Wx + (size_t)(n0 + aRow) * DIN + aK4 * 4;

    float acc[8][4] = {};

    for (int k0 = 0; k0 < DIN; k0 += 16) {
        float4 av0 = __ldg((const float4*)(aG0 + k0));
        float4 av1 = __ldg((const float4*)(aG1 + k0));
        float4 bv  = __ldg((const float4*)(bG + k0));
        __syncthreads();
        As[aK4 * 4 + 0][aRow]      = av0.x;
        As[aK4 * 4 + 1][aRow]      = av0.y;
        As[aK4 * 4 + 2][aRow]      = av0.z;
        As[aK4 * 4 + 3][aRow]      = av0.w;
        As[aK4 * 4 + 0][aRow + 64] = av1.x;
        As[aK4 * 4 + 1][aRow + 64] = av1.y;
        As[aK4 * 4 + 2][aRow + 64] = av1.z;
        As[aK4 * 4 + 3][aRow + 64] = av1.w;
        Bs[aK4 * 4 + 0][aRow] = bv.x;
        Bs[aK4 * 4 + 1][aRow] = bv.y;
        Bs[aK4 * 4 + 2][aRow] = bv.z;
        Bs[aK4 * 4 + 3][aRow] = bv.w;
        __syncthreads();

        #pragma unroll
        for (int kk = 0; kk < 16; ++kk) {
            float a[8], b[4];
            *(float4*)&a[0] = *(const float4*)&As[kk][ty << 3];
            *(float4*)&a[4] = *(const float4*)&As[kk][(ty << 3) + 4];
            *(float4*)&b[0] = *(const float4*)&Bs[kk][tx << 2];
            #pragma unroll
            for (int i = 0; i < 8; ++i)
                #pragma unroll
                for (int j = 0; j < 4; ++j)
                    acc[i][j] = fmaf(a[i], b[j], acc[i][j]);
        }
    }

    const int n = n0 + (tx << 2);
    float4 bxv = *(const float4*)(bx + n);
    float4 bhv = *(const float4*)(bh + n);
    const float b0f = bxv.x + bhv.x, b1f = bxv.y + bhv.y;
    const float b2f = bxv.z + bhv.z, b3f = bxv.w + bhv.w;

    #pragma unroll
    for (int i = 0; i < 8; ++i) {
        float4 o;
        o.x = acc[i][0] + b0f;
        o.y = acc[i][1] + b1f;
        o.z = acc[i][2] + b2f;
        o.w = acc[i][3] + b3f;
        *(float4*)(out + (size_t)(m0 + (ty << 3) + i) * HID + n) = o;
    }
}

// ---------------- Phase 2: persistent scan ------------------------------------
// 128 CTAs: (bt 0..7) x (ht 0..15). CTA = 16 batch rows x 32 output cols.
// 256 threads = 8 warps; warp w handles K-chunk [w*64, w*64+64).
// Thread (g = lane&7, q = lane>>3): cols j0 + g + 8*jc, rows b0 + q + 4*i.
// 16 accumulators/thread; partials reduced through smem.
__global__ void __launch_bounds__(SCAN_THREADS, 1) rnn_scan_kernel(
    const float* __restrict__ h0, const float* __restrict__ Wh,
    float* __restrict__ out)
{
    extern __shared__ float sm[];
    float* ws  = sm;                        // [32 cols][516]
    float* hs  = sm + WS_FLOATS;            // [16 rows][516]
    float* red = sm + WS_FLOATS + HS_FLOATS;

    const int tid  = threadIdx.x;
    const int lane = tid & 31;
    const int w    = tid >> 5;              // warp 0..7
    const int g    = lane & 7;
    const int q    = lane >> 3;
    const int bt = blockIdx.x >> 4;
    const int ht = blockIdx.x & 15;
    const int b0 = bt << 4;
    const int j0 = ht << 5;

    // init g_h[0] <- input h
    {
        int idx = blockIdx.x * SCAN_THREADS + tid;
        if (idx < (BATCH * HID) / 4)
            ((float4*)g_h[0])[idx] = __ldg((const float4*)h0 + idx);
    }
    // load Wh slice: ws[j'][k] = Wh[j0+j'][k], padded stride 516
    {
        const float4* whp = (const float4*)(Wh + (size_t)j0 * HID);
        float4* ws4 = (float4*)ws;
        for (int i = tid; i < 32 * 128; i += SCAN_THREADS) {
            int j = i >> 7, k4 = i & 127;
            ws4[j * WS_STRIDE_F4 + k4] = __ldg(whp + j * 128 + k4);
        }
    }
    grid_barrier();

    // per-thread column/row pointers into smem (f4 units), at warp's k-chunk
    const int kbase = w * 16;   // in f4 units (k-chunk 64 floats)
    const float4* wc[4];
    const float4* hr[4];
    #pragma unroll
    for (int jc = 0; jc < 4; ++jc)
        wc[jc] = (const float4*)ws + (g + 8 * jc) * WS_STRIDE_F4 + kbase;
    #pragma unroll
    for (int i = 0; i < 4; ++i)
        hr[i] = (const float4*)hs + (q + 4 * i) * HS_STRIDE_F4 + kbase;

    // epilogue mapping: 2 outputs per thread
    const int r1 = tid >> 5;                 // rows r1 and r1+8
    const int ce = tid & 31;                 // col
    const int je = j0 + ce;

    int p = 0;

    for (int t = 0; t < L_STEPS; ++t) {
        float* gout = out + (size_t)t * (BATCH * HID);
        // prefetch xp for this thread's two outputs (only this thread touches them)
        float xp1 = gout[(size_t)(b0 + r1) * HID + je];
        float xp2 = gout[(size_t)(b0 + r1 + 8) * HID + je];

        // stage h tile (16 rows x 512) into smem, padded
        {
            const float4* gh = (const float4*)(g_h[p] + b0 * HID);
            float4* hs4 = (float4*)hs;
            #pragma unroll
            for (int n = 0; n < 8; ++n) {
                int i = tid + n * SCAN_THREADS;
                int row = i >> 7, k4 = i & 127;
                hs4[row * HS_STRIDE_F4 + k4] = __ldcg(gh + i);
            }
        }
        __syncthreads();

        float acc[4][4];
        #pragma unroll
        for (int i = 0; i < 4; ++i)
            #pragma unroll
            for (int jc = 0; jc < 4; ++jc)
                acc[i][jc] = 0.f;

        #pragma unroll 4
        for (int kk = 0; kk < 16; ++kk) {
            float4 wv[4], hv[4];
            #pragma unroll
            for (int jc = 0; jc < 4; ++jc) wv[jc] = wc[jc][kk];
            #pragma unroll
            for (int i = 0; i < 4; ++i)  hv[i] = hr[i][kk];
            #pragma unroll
            for (int i = 0; i < 4; ++i) {
                #pragma unroll
                for (int jc = 0; jc < 4; ++jc) {
                    acc[i][jc] = fmaf(hv[i].x, wv[jc].x, acc[i][jc]);
                    acc[i][jc] = fmaf(hv[i].y, wv[jc].y, acc[i][jc]);
                    acc[i][jc] = fmaf(hv[i].z, wv[jc].z, acc[i][jc]);
                    acc[i][jc] = fmaf(hv[i].w, wv[jc].w, acc[i][jc]);
                }
            }
        }

        // store K-partials: red[w][ (q+4i)*36 + (g+8jc) ]
        {
            float* rw = red + w * RED_WARP;
            #pragma unroll
            for (int i = 0; i < 4; ++i)
                #pragma unroll
                for (int jc = 0; jc < 4; ++jc)
                    rw[(q + 4 * i) * RED_ROW + (g + 8 * jc)] = acc[i][jc];
        }
        __syncthreads();

        // reduce 8 partials + epilogue: thread handles (r1, ce) and (r1+8, ce)
        {
            float s1 = 0.f, s2 = 0.f;
            #pragma unroll
            for (int ww = 0; ww < 8; ++ww) {
                s1 += red[ww * RED_WARP + r1 * RED_ROW + ce];
                s2 += red[ww * RED_WARP + (r1 + 8) * RED_ROW + ce];
            }
            float hn1 = tanhf(s1 + xp1);
            float hn2 = tanhf(s2 + xp2);
            float* ghn = g_h[p ^ 1];
            const size_t o1 = (size_t)(b0 + r1) * HID + je;
            const size_t o2 = (size_t)(b0 + r1 + 8) * HID + je;
            gout[o1] = hn1;  gout[o2] = hn2;
            ghn[o1]  = hn1;  ghn[o2]  = hn2;
            if (t == L_STEPS - 1) {
                out[(size_t)L_STEPS * BATCH * HID + o1] = hn1;
                out[(size_t)L_STEPS * BATCH * HID + o2] = hn2;
            }
        }

        if (t != L_STEPS - 1) grid_barrier();
        p ^= 1;
    }
}

// ---------------- launch -------------------------------------------------------
extern "C" void kernel_launch(void* const* d_in, const int* in_sizes, int n_in,
                              void* d_out, int out_size)
{
    const float* x   = (const float*)d_in[0];
    const float* h0  = (const float*)d_in[1];
    const float* Wxw = (const float*)d_in[2];
    const float* Wxb = (const float*)d_in[3];
    const float* Whw = (const float*)d_in[4];
    const float* Whb = (const float*)d_in[5];
    float* out = (float*)d_out;

    dim3 g1(HID / 64, (L_STEPS * BATCH) / 128);
    xproj_kernel<<<g1, 256>>>(x, Wxw, Wxb, Whb, out);

    cudaFuncSetAttribute(rnn_scan_kernel,
                         cudaFuncAttributeMaxDynamicSharedMemorySize, SMEM_BYTES);
    rnn_scan_kernel<<<SCAN_BLOCKS, SCAN_THREADS, SMEM_BYTES>>>(h0, Whw, out);
}

// round 5
// speedup vs baseline: 2.0567x; 1.1668x over previous
#include <cuda_runtime.h>
#include <cuda_bf16.h>
#include <stdint.h>
#include <math.h>

#define L_STEPS 512
#define BATCH   128
#define HID     512
#define DIN     512

// ---------------- device scratch ----------------
__device__ __nv_bfloat16 g_h_hi[2][BATCH * HID];
__device__ __nv_bfloat16 g_h_lo[2][BATCH * HID];
__device__ unsigned g_bar_arrive = 0;              // init (full-grid) barrier
__device__ volatile unsigned g_bar_gen = 0;
__device__ unsigned g_garr[8 * 32];                // per-bt-group barriers (padded lines)
__device__ volatile unsigned g_ggen[8 * 32];

#define SCAN_BLOCKS  128
#define SCAN_THREADS 256

// smem (bytes): Whi[32][520]bf16, Wlo, hhi[16][520]bf16, hlo
#define W_STRIDE 520
#define H_STRIDE 520
#define WS_BYTES (32 * W_STRIDE * 2)     // 33280
#define HS_BYTES (16 * H_STRIDE * 2)     // 16640
#define OFF_WHI  0
#define OFF_WLO  (WS_BYTES)
#define OFF_HHI  (2 * WS_BYTES)
#define OFF_HLO  (2 * WS_BYTES + HS_BYTES)
#define SMEM_BYTES (2 * WS_BYTES + 2 * HS_BYTES)   // 99840

// ---------------- barriers ----------------
__device__ __forceinline__ void full_grid_barrier() {
    __threadfence();
    __syncthreads();
    if (threadIdx.x == 0) {
        unsigned gen = g_bar_gen;
        if (atomicAdd(&g_bar_arrive, 1u) == SCAN_BLOCKS - 1) {
            g_bar_arrive = 0;
            __threadfence();
            g_bar_gen = gen + 1;
        } else {
            while (g_bar_gen == gen) { __nanosleep(32); }
        }
    }
    __syncthreads();
}

__device__ __forceinline__ void group_barrier(int grp) {
    __threadfence();
    __syncthreads();
    if (threadIdx.x == 0) {
        unsigned* arr = &g_garr[grp * 32];
        volatile unsigned* gen = &g_ggen[grp * 32];
        unsigned g = *gen;
        if (atomicAdd(arr, 1u) == 15) {
            *arr = 0;
            __threadfence();
            *gen = g + 1;
        } else {
            while (*gen == g) { __nanosleep(20); }
        }
    }
    __syncthreads();
}

// ---------------- mma / ldmatrix helpers ----------------
__device__ __forceinline__ void mma_bf16(float& c0, float& c1, float& c2, float& c3,
                                         uint32_t a0, uint32_t a1, uint32_t a2, uint32_t a3,
                                         uint32_t b0, uint32_t b1) {
    asm volatile(
        "mma.sync.aligned.m16n8k16.row.col.f32.bf16.bf16.f32 "
        "{%0,%1,%2,%3}, {%4,%5,%6,%7}, {%8,%9}, {%0,%1,%2,%3};"
        : "+f"(c0), "+f"(c1), "+f"(c2), "+f"(c3)
        : "r"(a0), "r"(a1), "r"(a2), "r"(a3), "r"(b0), "r"(b1));
}
__device__ __forceinline__ void ldsm_x4(uint32_t r[4], uint32_t addr) {
    asm volatile("ldmatrix.sync.aligned.m8n8.x4.shared.b16 {%0,%1,%2,%3}, [%4];"
                 : "=r"(r[0]), "=r"(r[1]), "=r"(r[2]), "=r"(r[3]) : "r"(addr));
}
__device__ __forceinline__ void ldsm_x2(uint32_t r[2], uint32_t addr) {
    asm volatile("ldmatrix.sync.aligned.m8n8.x2.shared.b16 {%0,%1}, [%2];"
                 : "=r"(r[0]), "=r"(r[1]) : "r"(addr));
}

__device__ __forceinline__ void split_bf16(float v, __nv_bfloat16& hi, __nv_bfloat16& lo) {
    hi = __float2bfloat16(v);
    lo = __float2bfloat16(v - __bfloat162float(hi));
}

// ---------------- Phase 1: xproj (fp32 SIMT) -----------------------
__global__ void __launch_bounds__(256) xproj_kernel(
    const float* __restrict__ x, const float* __restrict__ Wx,
    const float* __restrict__ bx, const float* __restrict__ bh,
    float* __restrict__ out)
{
    __shared__ float As[16][128];
    __shared__ float Bs[16][64];

    const int tid = threadIdx.x;
    const int tx = tid & 15;
    const int ty = tid >> 4;
    const int m0 = blockIdx.y << 7;
    const int n0 = blockIdx.x << 6;

    const int aRow = tid >> 2;
    const int aK4  = tid & 3;
    const float* aG0 = x + (size_t)(m0 + aRow) * DIN + aK4 * 4;
    const float* aG1 = aG0 + (size_t)64 * DIN;
    const float* bG = Wx + (size_t)(n0 + aRow) * DIN + aK4 * 4;

    float acc[8][4] = {};

    for (int k0 = 0; k0 < DIN; k0 += 16) {
        float4 av0 = __ldg((const float4*)(aG0 + k0));
        float4 av1 = __ldg((const float4*)(aG1 + k0));
        float4 bv  = __ldg((const float4*)(bG + k0));
        __syncthreads();
        As[aK4 * 4 + 0][aRow]      = av0.x;
        As[aK4 * 4 + 1][aRow]      = av0.y;
        As[aK4 * 4 + 2][aRow]      = av0.z;
        As[aK4 * 4 + 3][aRow]      = av0.w;
        As[aK4 * 4 + 0][aRow + 64] = av1.x;
        As[aK4 * 4 + 1][aRow + 64] = av1.y;
        As[aK4 * 4 + 2][aRow + 64] = av1.z;
        As[aK4 * 4 + 3][aRow + 64] = av1.w;
        Bs[aK4 * 4 + 0][aRow] = bv.x;
        Bs[aK4 * 4 + 1][aRow] = bv.y;
        Bs[aK4 * 4 + 2][aRow] = bv.z;
        Bs[aK4 * 4 + 3][aRow] = bv.w;
        __syncthreads();

        #pragma unroll
        for (int kk = 0; kk < 16; ++kk) {
            float a[8], b[4];
            *(float4*)&a[0] = *(const float4*)&As[kk][ty << 3];
            *(float4*)&a[4] = *(const float4*)&As[kk][(ty << 3) + 4];
            *(float4*)&b[0] = *(const float4*)&Bs[kk][tx << 2];
            #pragma unroll
            for (int i = 0; i < 8; ++i)
                #pragma unroll
                for (int j = 0; j < 4; ++j)
                    acc[i][j] = fmaf(a[i], b[j], acc[i][j]);
        }
    }

    const int n = n0 + (tx << 2);
    float4 bxv = *(const float4*)(bx + n);
    float4 bhv = *(const float4*)(bh + n);
    const float b0f = bxv.x + bhv.x, b1f = bxv.y + bhv.y;
    const float b2f = bxv.z + bhv.z, b3f = bxv.w + bhv.w;

    #pragma unroll
    for (int i = 0; i < 8; ++i) {
        float4 o;
        o.x = acc[i][0] + b0f;
        o.y = acc[i][1] + b1f;
        o.z = acc[i][2] + b2f;
        o.w = acc[i][3] + b3f;
        *(float4*)(out + (size_t)(m0 + (ty << 3) + i) * HID + n) = o;
    }
}

// ---------------- Phase 2: persistent scan, bf16-split tensor cores -----------
// CTA (bt,ht): 16 batch rows (b0), 32 output cols (j0). Warps 0-3: MMA over
// n-tile of 8 cols each, full K in registers. Warps 4-7: staging only.
// Exchange h as bf16 hi/lo via global; barrier only among 16 CTAs of same bt.
__global__ void __launch_bounds__(SCAN_THREADS, 1) rnn_scan_kernel(
    const float* __restrict__ h0, const float* __restrict__ Wh,
    float* __restrict__ out)
{
    extern __shared__ char sm[];
    __nv_bfloat16* ws_hi = (__nv_bfloat16*)(sm + OFF_WHI);
    __nv_bfloat16* ws_lo = (__nv_bfloat16*)(sm + OFF_WLO);
    __nv_bfloat16* hs_hi = (__nv_bfloat16*)(sm + OFF_HHI);
    __nv_bfloat16* hs_lo = (__nv_bfloat16*)(sm + OFF_HLO);

    const int tid  = threadIdx.x;
    const int lane = tid & 31;
    const int w    = tid >> 5;
    const int bt = blockIdx.x >> 4;
    const int ht = blockIdx.x & 15;
    const int b0 = bt << 4;
    const int j0 = ht << 5;

    // ---- init: split h0 into bf16 hi/lo (whole grid cooperates) ----
    {
        int gtid = blockIdx.x * SCAN_THREADS + tid;
        #pragma unroll
        for (int r = 0; r < 2; ++r) {
            int i = gtid + r * (SCAN_BLOCKS * SCAN_THREADS);
            float v = __ldg(h0 + i);
            __nv_bfloat16 hi, lo;
            split_bf16(v, hi, lo);
            g_h_hi[0][i] = hi;
            g_h_lo[0][i] = lo;
        }
    }
    // ---- init: split W slice rows j0..j0+31 into smem [n][k] ----
    for (int i = tid; i < 32 * HID; i += SCAN_THREADS) {
        int n = i >> 9, k = i & 511;
        float v = __ldg(Wh + (size_t)(j0 + n) * HID + k);
        __nv_bfloat16 hi, lo;
        split_bf16(v, hi, lo);
        ws_hi[n * W_STRIDE + k] = hi;
        ws_lo[n * W_STRIDE + k] = lo;
    }
    full_grid_barrier();

    // ---- precompute ldmatrix base addresses ----
    uint32_t hs_hi_u = (uint32_t)__cvta_generic_to_shared(hs_hi);
    uint32_t hs_lo_u = (uint32_t)__cvta_generic_to_shared(hs_lo);
    uint32_t ws_hi_u = (uint32_t)__cvta_generic_to_shared(ws_hi);
    uint32_t ws_lo_u = (uint32_t)__cvta_generic_to_shared(ws_lo);

    // A (16x16 tile): lanes 0-7 rows 0-7 @k0 | 8-15 rows 8-15 @k0 | 16-23 rows0-7 @+8 | 24-31 rows8-15 @+8
    const int arow  = (lane & 7) + ((lane >> 3) & 1) * 8;
    const int akoff = (lane >> 4) * 16;                   // bytes (+8 bf16)
    const uint32_t aHiBase = hs_hi_u + arow * (H_STRIDE * 2) + akoff;
    const uint32_t aLoBase = hs_lo_u + arow * (H_STRIDE * 2) + akoff;
    // B (8 cols x 16 k): lanes 0-7 n-rows @k0 | 8-15 n-rows @k0+8
    const int brow  = 8 * w + (lane & 7);
    const int bkoff = ((lane >> 3) & 1) * 16;
    const uint32_t bHiBase = ws_hi_u + brow * (W_STRIDE * 2) + bkoff;
    const uint32_t bLoBase = ws_lo_u + brow * (W_STRIDE * 2) + bkoff;

    // epilogue mapping (MMA warps): C frag (r=lane>>2, c=2*(lane&3))
    const int er = lane >> 2;
    const int ec = 2 * (lane & 3);
    const int jcol = j0 + 8 * w + ec;
    const size_t o1 = (size_t)(b0 + er) * HID + jcol;
    const size_t o2 = (size_t)(b0 + er + 8) * HID + jcol;

    int p = 0;

    for (int t = 0; t < L_STEPS; ++t) {
        float* gout = out + (size_t)t * (BATCH * HID);
        float2 xp1, xp2;
        if (w < 4) {
            xp1 = *(const float2*)(gout + o1);
            xp2 = *(const float2*)(gout + o2);
        }

        // ---- stage h tile (16 rows) hi+lo into smem, padded stride ----
        {
            const float4* srcH = (const float4*)(g_h_hi[p] + b0 * HID);
            const float4* srcL = (const float4*)(g_h_lo[p] + b0 * HID);
            float4* dH = (float4*)hs_hi;
            float4* dL = (float4*)hs_lo;
            #pragma unroll
            for (int n = 0; n < 4; ++n) {
                int i = tid + n * SCAN_THREADS;       // 0..1023 (f4 of bf16)
                int row = i >> 6, c4 = i & 63;
                int d = row * 65 + c4;                // 65 f4 per padded row
                dH[d] = __ldcg(srcH + i);
                dL[d] = __ldcg(srcL + i);
            }
        }
        __syncthreads();

        if (w < 4) {
            float c0 = 0.f, c1 = 0.f, c2 = 0.f, c3 = 0.f;
            #pragma unroll 8
            for (int ki = 0; ki < 32; ++ki) {
                const uint32_t koff = ki * 32;        // 16 bf16 = 32 bytes
                uint32_t ah[4], al[4], bh[2], bl[2];
                ldsm_x4(ah, aHiBase + koff);
                ldsm_x4(al, aLoBase + koff);
                ldsm_x2(bh, bHiBase + koff);
                ldsm_x2(bl, bLoBase + koff);
                mma_bf16(c0, c1, c2, c3, ah[0], ah[1], ah[2], ah[3], bh[0], bh[1]);
                mma_bf16(c0, c1, c2, c3, ah[0], ah[1], ah[2], ah[3], bl[0], bl[1]);
                mma_bf16(c0, c1, c2, c3, al[0], al[1], al[2], al[3], bh[0], bh[1]);
            }

            // ---- epilogue: tanh(acc + xp); write fp32 hAll + bf16 hi/lo state ----
            float hn0 = tanhf(c0 + xp1.x);
            float hn1 = tanhf(c1 + xp1.y);
            float hn2 = tanhf(c2 + xp2.x);
            float hn3 = tanhf(c3 + xp2.y);

            *(float2*)(gout + o1) = make_float2(hn0, hn1);
            *(float2*)(gout + o2) = make_float2(hn2, hn3);

            __nv_bfloat16 h0b, l0b, h1b, l1b, h2b, l2b, h3b, l3b;
            split_bf16(hn0, h0b, l0b);
            split_bf16(hn1, h1b, l1b);
            split_bf16(hn2, h2b, l2b);
            split_bf16(hn3, h3b, l3b);

            __nv_bfloat16* ghh = g_h_hi[p ^ 1];
            __nv_bfloat16* ghl = g_h_lo[p ^ 1];
            *(__nv_bfloat162*)(ghh + o1) = __nv_bfloat162(h0b, h1b);
            *(__nv_bfloat162*)(ghh + o2) = __nv_bfloat162(h2b, h3b);
            *(__nv_bfloat162*)(ghl + o1) = __nv_bfloat162(l0b, l1b);
            *(__nv_bfloat162*)(ghl + o2) = __nv_bfloat162(l2b, l3b);

            if (t == L_STEPS - 1) {
                float* hlast = out + (size_t)L_STEPS * BATCH * HID;
                *(float2*)(hlast + o1) = make_float2(hn0, hn1);
                *(float2*)(hlast + o2) = make_float2(hn2, hn3);
            }
        }

        if (t != L_STEPS - 1) group_barrier(bt);
        p ^= 1;
    }
}

// ---------------- launch -------------------------------------------------------
extern "C" void kernel_launch(void* const* d_in, const int* in_sizes, int n_in,
                              void* d_out, int out_size)
{
    const float* x   = (const float*)d_in[0];
    const float* h0  = (const float*)d_in[1];
    const float* Wxw = (const float*)d_in[2];
    const float* Wxb = (const float*)d_in[3];
    const float* Whw = (const float*)d_in[4];
    const float* Whb = (const float*)d_in[5];
    float* out = (float*)d_out;

    dim3 g1(HID / 64, (L_STEPS * BATCH) / 128);
    xproj_kernel<<<g1, 256>>>(x, Wxw, Wxb, Whb, out);

    cudaFuncSetAttribute(rnn_scan_kernel,
                         cudaFuncAttributeMaxDynamicSharedMemorySize, SMEM_BYTES);
    rnn_scan_kernel<<<SCAN_BLOCKS, SCAN_THREADS, SMEM_BYTES>>>(h0, Whw, out);
}

// round 6
// speedup vs baseline: 2.7449x; 1.3346x over previous
#include <cuda_runtime.h>
#include <cuda_bf16.h>
#include <stdint.h>
#include <math.h>

#define L_STEPS 512
#define BATCH   128
#define HID     512
#define DIN     512

// ---------------- device scratch ----------------
__device__ __nv_bfloat16 g_h_hi[2][BATCH * HID];
__device__ __nv_bfloat16 g_h_lo[2][BATCH * HID];
__device__ unsigned g_bar_arrive = 0;
__device__ volatile unsigned g_bar_gen = 0;
__device__ unsigned g_garr[8 * 32];
__device__ unsigned g_ggen[8 * 32];

#define SCAN_BLOCKS  128
#define SCAN_THREADS 256

// scan smem: Whi[32][520]bf16, Wlo, hhi[16][520]bf16, hlo
#define W_STRIDE 520
#define H_STRIDE 520
#define WS_BYTES (32 * W_STRIDE * 2)
#define HS_BYTES (16 * H_STRIDE * 2)
#define OFF_WHI  0
#define OFF_WLO  (WS_BYTES)
#define OFF_HHI  (2 * WS_BYTES)
#define OFF_HLO  (2 * WS_BYTES + HS_BYTES)
#define SMEM_BYTES (2 * WS_BYTES + 2 * HS_BYTES)

// xproj smem: 4 tiles of [128][72] bf16
#define XP_STRIDE 72
#define XP_TILE_BYTES (128 * XP_STRIDE * 2)     // 18432
#define XP_AHI 0
#define XP_ALO (XP_TILE_BYTES)
#define XP_BHI (2 * XP_TILE_BYTES)
#define XP_BLO (3 * XP_TILE_BYTES)
#define XP_SMEM (4 * XP_TILE_BYTES)             // 73728

// ---------------- barriers ----------------
__device__ __forceinline__ void full_grid_barrier() {
    __threadfence();
    __syncthreads();
    if (threadIdx.x == 0) {
        unsigned gen = g_bar_gen;
        if (atomicAdd(&g_bar_arrive, 1u) == SCAN_BLOCKS - 1) {
            g_bar_arrive = 0;
            __threadfence();
            g_bar_gen = gen + 1;
        } else {
            while (g_bar_gen == gen) { __nanosleep(32); }
        }
    }
    __syncthreads();
}

// release/acquire group barrier: 16 CTAs of the same bt group
__device__ __forceinline__ void group_barrier(int grp) {
    __syncthreads();
    if (threadIdx.x == 0) {
        unsigned* arr = &g_garr[grp * 32];
        unsigned* gen = &g_ggen[grp * 32];
        unsigned g;
        asm volatile("ld.relaxed.gpu.u32 %0, [%1];" : "=r"(g) : "l"(gen));
        unsigned old;
        asm volatile("atom.add.acq_rel.gpu.u32 %0, [%1], 1;" : "=r"(old) : "l"(arr));
        if (old == 15) {
            asm volatile("st.relaxed.gpu.u32 [%0], 0;" :: "l"(arr));
            unsigned ng = g + 1;
            asm volatile("st.release.gpu.u32 [%0], %1;" :: "l"(gen), "r"(ng));
        } else {
            unsigned cur;
            do {
                __nanosleep(20);
                asm volatile("ld.acquire.gpu.u32 %0, [%1];" : "=r"(cur) : "l"(gen));
            } while (cur == g);
        }
    }
    __syncthreads();
}

// ---------------- mma / ldmatrix helpers ----------------
__device__ __forceinline__ void mma_bf16(float* c,
                                         uint32_t a0, uint32_t a1, uint32_t a2, uint32_t a3,
                                         uint32_t b0, uint32_t b1) {
    asm volatile(
        "mma.sync.aligned.m16n8k16.row.col.f32.bf16.bf16.f32 "
        "{%0,%1,%2,%3}, {%4,%5,%6,%7}, {%8,%9}, {%0,%1,%2,%3};"
        : "+f"(c[0]), "+f"(c[1]), "+f"(c[2]), "+f"(c[3])
        : "r"(a0), "r"(a1), "r"(a2), "r"(a3), "r"(b0), "r"(b1));
}
__device__ __forceinline__ void ldsm_x4(uint32_t r[4], uint32_t addr) {
    asm volatile("ldmatrix.sync.aligned.m8n8.x4.shared.b16 {%0,%1,%2,%3}, [%4];"
                 : "=r"(r[0]), "=r"(r[1]), "=r"(r[2]), "=r"(r[3]) : "r"(addr));
}
__device__ __forceinline__ void ldsm_x2(uint32_t r[2], uint32_t addr) {
    asm volatile("ldmatrix.sync.aligned.m8n8.x2.shared.b16 {%0,%1}, [%2];"
                 : "=r"(r[0]), "=r"(r[1]) : "r"(addr));
}
__device__ __forceinline__ void split_bf16(float v, __nv_bfloat16& hi, __nv_bfloat16& lo) {
    hi = __float2bfloat16(v);
    lo = __float2bfloat16(v - __bfloat162float(hi));
}

// ---------------- Phase 1: xproj via bf16-split MMA ---------------------------
// CTA tile 128(M) x 128(N), K-chunks of 64. 8 warps: wm=w&3 (32 rows), wn=w>>2 (64 cols).
__global__ void __launch_bounds__(256, 1) xproj_mma_kernel(
    const float* __restrict__ x, const float* __restrict__ Wx,
    const float* __restrict__ bx, const float* __restrict__ bh,
    float* __restrict__ out)
{
    extern __shared__ char sm[];
    __nv_bfloat16* a_hi = (__nv_bfloat16*)(sm + XP_AHI);
    __nv_bfloat16* a_lo = (__nv_bfloat16*)(sm + XP_ALO);
    __nv_bfloat16* b_hi = (__nv_bfloat16*)(sm + XP_BHI);
    __nv_bfloat16* b_lo = (__nv_bfloat16*)(sm + XP_BLO);

    const int tid  = threadIdx.x;
    const int lane = tid & 31;
    const int w    = tid >> 5;
    const int wm   = w & 3;
    const int wn   = w >> 2;
    const int m0   = blockIdx.y << 7;
    const int n0   = blockIdx.x << 7;

    const uint32_t aHiU = (uint32_t)__cvta_generic_to_shared(a_hi);
    const uint32_t aLoU = (uint32_t)__cvta_generic_to_shared(a_lo);
    const uint32_t bHiU = (uint32_t)__cvta_generic_to_shared(b_hi);
    const uint32_t bLoU = (uint32_t)__cvta_generic_to_shared(b_lo);

    // A frag lane mapping (m16k16 via ldsm x4)
    const int arow   = (lane & 7) + ((lane >> 3) & 1) * 8;
    const int akoff  = (lane >> 4) * 16;                  // bytes
    // B frag lane mapping (two n8 frags via ldsm x4)
    const int bn     = ((lane >> 4) << 3) + (lane & 7);
    const int bkoff  = ((lane >> 3) & 1) * 16;

    uint32_t aHiB[2], aLoB[2];
    #pragma unroll
    for (int mi = 0; mi < 2; ++mi) {
        int r = (wm << 5) + (mi << 4) + arow;
        aHiB[mi] = aHiU + r * (XP_STRIDE * 2) + akoff;
        aLoB[mi] = aLoU + r * (XP_STRIDE * 2) + akoff;
    }

    float acc[2][8][4];
    #pragma unroll
    for (int mi = 0; mi < 2; ++mi)
        #pragma unroll
        for (int nf = 0; nf < 8; ++nf)
            #pragma unroll
            for (int r = 0; r < 4; ++r) acc[mi][nf][r] = 0.f;

    const int ldRow = tid >> 4;          // 0..15 (x8 => 128 rows)
    const int ldC4  = tid & 15;          // f4 col within 64-chunk

    for (int kc = 0; kc < DIN; kc += 64) {
        __syncthreads();
        // load + split A (x) and B (Wx) tiles: 8 rows-of-16 f4 each
        #pragma unroll
        for (int t = 0; t < 8; ++t) {
            const int row = ldRow + (t << 4);
            float4 av = __ldg((const float4*)(x + (size_t)(m0 + row) * DIN + kc) + ldC4);
            float4 bv = __ldg((const float4*)(Wx + (size_t)(n0 + row) * DIN + kc) + ldC4);
            __nv_bfloat16 h0, l0, h1, l1, h2, l2, h3, l3;
            split_bf16(av.x, h0, l0); split_bf16(av.y, h1, l1);
            split_bf16(av.z, h2, l2); split_bf16(av.w, h3, l3);
            __nv_bfloat162* pH = (__nv_bfloat162*)(a_hi + row * XP_STRIDE + (ldC4 << 2));
            __nv_bfloat162* pL = (__nv_bfloat162*)(a_lo + row * XP_STRIDE + (ldC4 << 2));
            pH[0] = __nv_bfloat162(h0, h1); pH[1] = __nv_bfloat162(h2, h3);
            pL[0] = __nv_bfloat162(l0, l1); pL[1] = __nv_bfloat162(l2, l3);
            split_bf16(bv.x, h0, l0); split_bf16(bv.y, h1, l1);
            split_bf16(bv.z, h2, l2); split_bf16(bv.w, h3, l3);
            pH = (__nv_bfloat162*)(b_hi + row * XP_STRIDE + (ldC4 << 2));
            pL = (__nv_bfloat162*)(b_lo + row * XP_STRIDE + (ldC4 << 2));
            pH[0] = __nv_bfloat162(h0, h1); pH[1] = __nv_bfloat162(h2, h3);
            pL[0] = __nv_bfloat162(l0, l1); pL[1] = __nv_bfloat162(l2, l3);
        }
        __syncthreads();

        #pragma unroll
        for (int k16 = 0; k16 < 4; ++k16) {
            const uint32_t ko = k16 * 32;
            uint32_t ah[2][4], al[2][4];
            ldsm_x4(ah[0], aHiB[0] + ko);
            ldsm_x4(ah[1], aHiB[1] + ko);
            ldsm_x4(al[0], aLoB[0] + ko);
            ldsm_x4(al[1], aLoB[1] + ko);
            #pragma unroll
            for (int np = 0; np < 4; ++np) {
                const uint32_t bOff =
                    ((wn << 6) + (np << 4) + bn) * (XP_STRIDE * 2) + bkoff + ko;
                uint32_t bh4[4], bl4[4];
                ldsm_x4(bh4, bHiU + bOff);
                ldsm_x4(bl4, bLoU + bOff);
                #pragma unroll
                for (int mi = 0; mi < 2; ++mi) {
                    #pragma unroll
                    for (int nf = 0; nf < 2; ++nf) {
                        float* c = acc[mi][(np << 1) + nf];
                        mma_bf16(c, ah[mi][0], ah[mi][1], ah[mi][2], ah[mi][3],
                                 bh4[2 * nf], bh4[2 * nf + 1]);
                        mma_bf16(c, ah[mi][0], ah[mi][1], ah[mi][2], ah[mi][3],
                                 bl4[2 * nf], bl4[2 * nf + 1]);
                        mma_bf16(c, al[mi][0], al[mi][1], al[mi][2], al[mi][3],
                                 bh4[2 * nf], bh4[2 * nf + 1]);
                    }
                }
            }
        }
    }

    // epilogue: add bias (bx+bh), write fp32
    const int er = lane >> 2;
    const int ec = (lane & 3) << 1;
    float bb[8][2];
    #pragma unroll
    for (int nf = 0; nf < 8; ++nf) {
        int gn = n0 + (wn << 6) + (nf << 3) + ec;
        bb[nf][0] = __ldg(bx + gn) + __ldg(bh + gn);
        bb[nf][1] = __ldg(bx + gn + 1) + __ldg(bh + gn + 1);
    }
    #pragma unroll
    for (int mi = 0; mi < 2; ++mi) {
        const int gm = m0 + (wm << 5) + (mi << 4) + er;
        #pragma unroll
        for (int nf = 0; nf < 8; ++nf) {
            const int gn = n0 + (wn << 6) + (nf << 3) + ec;
            float* c = acc[mi][nf];
            *(float2*)(out + (size_t)gm * HID + gn) =
                make_float2(c[0] + bb[nf][0], c[1] + bb[nf][1]);
            *(float2*)(out + (size_t)(gm + 8) * HID + gn) =
                make_float2(c[2] + bb[nf][0], c[3] + bb[nf][1]);
        }
    }
}

// ---------------- Phase 2: persistent scan, bf16-split MMA --------------------
__global__ void __launch_bounds__(SCAN_THREADS, 1) rnn_scan_kernel(
    const float* __restrict__ h0, const float* __restrict__ Wh,
    float* __restrict__ out)
{
    extern __shared__ char sm[];
    __nv_bfloat16* ws_hi = (__nv_bfloat16*)(sm + OFF_WHI);
    __nv_bfloat16* ws_lo = (__nv_bfloat16*)(sm + OFF_WLO);
    __nv_bfloat16* hs_hi = (__nv_bfloat16*)(sm + OFF_HHI);
    __nv_bfloat16* hs_lo = (__nv_bfloat16*)(sm + OFF_HLO);

    const int tid  = threadIdx.x;
    const int lane = tid & 31;
    const int w    = tid >> 5;
    const int bt = blockIdx.x >> 4;
    const int ht = blockIdx.x & 15;
    const int b0 = bt << 4;
    const int j0 = ht << 5;

    // init: split h0 into bf16 hi/lo
    {
        int gtid = blockIdx.x * SCAN_THREADS + tid;
        #pragma unroll
        for (int r = 0; r < 2; ++r) {
            int i = gtid + r * (SCAN_BLOCKS * SCAN_THREADS);
            float v = __ldg(h0 + i);
            __nv_bfloat16 hi, lo;
            split_bf16(v, hi, lo);
            g_h_hi[0][i] = hi;
            g_h_lo[0][i] = lo;
        }
    }
    // init: split W slice rows j0..j0+31 into smem [n][k]
    for (int i = tid; i < 32 * HID; i += SCAN_THREADS) {
        int n = i >> 9, k = i & 511;
        float v = __ldg(Wh + (size_t)(j0 + n) * HID + k);
        __nv_bfloat16 hi, lo;
        split_bf16(v, hi, lo);
        ws_hi[n * W_STRIDE + k] = hi;
        ws_lo[n * W_STRIDE + k] = lo;
    }
    full_grid_barrier();

    uint32_t hs_hi_u = (uint32_t)__cvta_generic_to_shared(hs_hi);
    uint32_t hs_lo_u = (uint32_t)__cvta_generic_to_shared(hs_lo);
    uint32_t ws_hi_u = (uint32_t)__cvta_generic_to_shared(ws_hi);
    uint32_t ws_lo_u = (uint32_t)__cvta_generic_to_shared(ws_lo);

    const int arow  = (lane & 7) + ((lane >> 3) & 1) * 8;
    const int akoff = (lane >> 4) * 16;
    const uint32_t aHiBase = hs_hi_u + arow * (H_STRIDE * 2) + akoff;
    const uint32_t aLoBase = hs_lo_u + arow * (H_STRIDE * 2) + akoff;
    const int brow  = 8 * w + (lane & 7);
    const int bkoff = ((lane >> 3) & 1) * 16;
    const uint32_t bHiBase = ws_hi_u + brow * (W_STRIDE * 2) + bkoff;
    const uint32_t bLoBase = ws_lo_u + brow * (W_STRIDE * 2) + bkoff;

    const int er = lane >> 2;
    const int ec = 2 * (lane & 3);
    const int jcol = j0 + 8 * w + ec;
    const size_t o1 = (size_t)(b0 + er) * HID + jcol;
    const size_t o2 = (size_t)(b0 + er + 8) * HID + jcol;

    int p = 0;

    for (int t = 0; t < L_STEPS; ++t) {
        float* gout = out + (size_t)t * (BATCH * HID);
        float2 xp1, xp2;
        if (w < 4) {
            xp1 = *(const float2*)(gout + o1);
            xp2 = *(const float2*)(gout + o2);
        }

        // stage h tile (16 rows) hi+lo into smem
        {
            const float4* srcH = (const float4*)(g_h_hi[p] + b0 * HID);
            const float4* srcL = (const float4*)(g_h_lo[p] + b0 * HID);
            float4* dH = (float4*)hs_hi;
            float4* dL = (float4*)hs_lo;
            #pragma unroll
            for (int n = 0; n < 4; ++n) {
                int i = tid + n * SCAN_THREADS;
                int row = i >> 6, c4 = i & 63;
                int d = row * 65 + c4;
                dH[d] = __ldcg(srcH + i);
                dL[d] = __ldcg(srcL + i);
            }
        }
        __syncthreads();

        if (w < 4) {
            // three independent accumulator chains (hh, hl, lh)
            float chh[4] = {0.f, 0.f, 0.f, 0.f};
            float chl[4] = {0.f, 0.f, 0.f, 0.f};
            float clh[4] = {0.f, 0.f, 0.f, 0.f};
            #pragma unroll 8
            for (int ki = 0; ki < 32; ++ki) {
                const uint32_t koff = ki * 32;
                uint32_t ah[4], al[4], bh[2], bl[2];
                ldsm_x4(ah, aHiBase + koff);
                ldsm_x4(al, aLoBase + koff);
                ldsm_x2(bh, bHiBase + koff);
                ldsm_x2(bl, bLoBase + koff);
                mma_bf16(chh, ah[0], ah[1], ah[2], ah[3], bh[0], bh[1]);
                mma_bf16(chl, ah[0], ah[1], ah[2], ah[3], bl[0], bl[1]);
                mma_bf16(clh, al[0], al[1], al[2], al[3], bh[0], bh[1]);
            }

            float hn0 = tanhf(chh[0] + chl[0] + clh[0] + xp1.x);
            float hn1 = tanhf(chh[1] + chl[1] + clh[1] + xp1.y);
            float hn2 = tanhf(chh[2] + chl[2] + clh[2] + xp2.x);
            float hn3 = tanhf(chh[3] + chl[3] + clh[3] + xp2.y);

            __nv_bfloat16 h0b, l0b, h1b, l1b, h2b, l2b, h3b, l3b;
            split_bf16(hn0, h0b, l0b);
            split_bf16(hn1, h1b, l1b);
            split_bf16(hn2, h2b, l2b);
            split_bf16(hn3, h3b, l3b);

            // state first (consumers wait on it), hAll after
            __nv_bfloat16* ghh = g_h_hi[p ^ 1];
            __nv_bfloat16* ghl = g_h_lo[p ^ 1];
            *(__nv_bfloat162*)(ghh + o1) = __nv_bfloat162(h0b, h1b);
            *(__nv_bfloat162*)(ghh + o2) = __nv_bfloat162(h2b, h3b);
            *(__nv_bfloat162*)(ghl + o1) = __nv_bfloat162(l0b, l1b);
            *(__nv_bfloat162*)(ghl + o2) = __nv_bfloat162(l2b, l3b);

            *(float2*)(gout + o1) = make_float2(hn0, hn1);
            *(float2*)(gout + o2) = make_float2(hn2, hn3);

            if (t == L_STEPS - 1) {
                float* hlast = out + (size_t)L_STEPS * BATCH * HID;
                *(float2*)(hlast + o1) = make_float2(hn0, hn1);
                *(float2*)(hlast + o2) = make_float2(hn2, hn3);
            }
        }

        if (t != L_STEPS - 1) group_barrier(bt);
        p ^= 1;
    }
}

// ---------------- launch -------------------------------------------------------
extern "C" void kernel_launch(void* const* d_in, const int* in_sizes, int n_in,
                              void* d_out, int out_size)
{
    const float* x   = (const float*)d_in[0];
    const float* h0  = (const float*)d_in[1];
    const float* Wxw = (const float*)d_in[2];
    const float* Wxb = (const float*)d_in[3];
    const float* Whw = (const float*)d_in[4];
    const float* Whb = (const float*)d_in[5];
    float* out = (float*)d_out;

    cudaFuncSetAttribute(xproj_mma_kernel,
                         cudaFuncAttributeMaxDynamicSharedMemorySize, XP_SMEM);
    dim3 g1(HID / 128, (L_STEPS * BATCH) / 128);
    xproj_mma_kernel<<<g1, 256, XP_SMEM>>>(x, Wxw, Wxb, Whb, out);

    cudaFuncSetAttribute(rnn_scan_kernel,
                         cudaFuncAttributeMaxDynamicSharedMemorySize, SMEM_BYTES);
    rnn_scan_kernel<<<SCAN_BLOCKS, SCAN_THREADS, SMEM_BYTES>>>(h0, Whw, out);
}